// round 8
// baseline (speedup 1.0000x reference)
#include <cuda_runtime.h>
#include <cuda_bf16.h>
#include <cstdint>

#define NN 50000
#define EE 400000
#define TT 4
#define DIN 64
#define DD 128
#define BG 64
#define NSTEPS 8
#define RTILES ((NN + 127) / 128)   // 391
#define NT (NN * TT)                // 200000 buckets
#define NBS ((NT + 1023) / 1024)    // 196 scan blocks

// ---------------- device scratch ----------------
__device__ float g_h [NN * DD];
__device__ float g_h1[NN * DD];
__device__ float g_a [NN * DD];
__device__ float g_rs[NN * DD];
__device__ float g_zs[NN * DD];
__device__ float g_in[NN * DD];
__device__ float g_hn[NN * DD];
__device__ float g_feats[BG * DD];
// CSR by (dst, etype)
__device__ int g_cnt [NT];
__device__ int g_scan[NT];
__device__ int g_off [NT + 1];
__device__ int g_part [256];
__device__ int g_part2[256];
__device__ int g_eoff[EE];
__device__ int g_gsrc[EE];               // payload: src*128 (h row offset)
// prepped bf16 hi/lo weights, B layout [col][k] (k contiguous)
__device__ __nv_bfloat16 g_Wt_hi [TT * DD * DD];
__device__ __nv_bfloat16 g_Wt_lo [TT * DD * DD];
__device__ __nv_bfloat16 g_Bih_hi[3 * DD * DD];
__device__ __nv_bfloat16 g_Bih_lo[3 * DD * DD];
__device__ __nv_bfloat16 g_Bhh_hi[3 * DD * DD];
__device__ __nv_bfloat16 g_Bhh_lo[3 * DD * DD];

// ---------------- helpers ----------------
__device__ __forceinline__ uint32_t smem_u32(const void* p) {
    return (uint32_t)__cvta_generic_to_shared(p);
}
__device__ __forceinline__ void ldsm_x4(uint32_t* r, uint32_t addr) {
    asm volatile("ldmatrix.sync.aligned.m8n8.x4.shared.b16 {%0,%1,%2,%3}, [%4];"
                 : "=r"(r[0]), "=r"(r[1]), "=r"(r[2]), "=r"(r[3]) : "r"(addr));
}
__device__ __forceinline__ void mma16816(float* d, const uint32_t* a, const uint32_t* b) {
    asm volatile(
        "mma.sync.aligned.m16n8k16.row.col.f32.bf16.bf16.f32 "
        "{%0,%1,%2,%3}, {%4,%5,%6,%7}, {%8,%9}, {%0,%1,%2,%3};"
        : "+f"(d[0]), "+f"(d[1]), "+f"(d[2]), "+f"(d[3])
        : "r"(a[0]), "r"(a[1]), "r"(a[2]), "r"(a[3]), "r"(b[0]), "r"(b[1]));
}
__device__ __forceinline__ void cp16(uint32_t dst, const void* src) {
    asm volatile("cp.async.cg.shared.global [%0], [%1], 16;" :: "r"(dst), "l"(src));
}
#define CP_COMMIT() asm volatile("cp.async.commit_group;" ::: "memory")
#define CP_WAIT0()  asm volatile("cp.async.wait_group 0;" ::: "memory")

#define TROW 136
#define RB   (TROW * 2)            // 272
#define AT128 (128 * RB)           // 34816
#define MS_SMEM (6 * AT128 + 2048) // msg kernel
#define G6SMEM  (6 * AT128)        // gates kernel (round-4 proven)

// fp32 -> hi/lo bf16 split (128 rows) into padded smem tiles
__device__ __forceinline__ void load_f32_split_tile(char* hi, char* lo,
        const float* __restrict__ src, int row0, int nrows, int tid) {
#pragma unroll
    for (int i = 0; i < 16; i++) {
        int f = tid + 256 * i;
        int r = f >> 5, c4 = (f & 31) * 4;
        int gr = row0 + r;
        float4 v = make_float4(0.f, 0.f, 0.f, 0.f);
        if (gr < nrows) v = *(const float4*)(src + (size_t)gr * DD + c4);
        __nv_bfloat16 h0 = __float2bfloat16(v.x), h1 = __float2bfloat16(v.y);
        __nv_bfloat16 h2 = __float2bfloat16(v.z), h3 = __float2bfloat16(v.w);
        __nv_bfloat16 l0 = __float2bfloat16(v.x - __bfloat162float(h0));
        __nv_bfloat16 l1 = __float2bfloat16(v.y - __bfloat162float(h1));
        __nv_bfloat16 l2 = __float2bfloat16(v.z - __bfloat162float(h2));
        __nv_bfloat16 l3 = __float2bfloat16(v.w - __bfloat162float(h3));
        __nv_bfloat162 hp0 = {h0, h1}, hp1 = {h2, h3};
        __nv_bfloat162 lp0 = {l0, l1}, lp1 = {l2, l3};
        uint32_t off = r * RB + c4 * 2;
        *(uint2*)(hi + off) = make_uint2(*(uint32_t*)&hp0, *(uint32_t*)&hp1);
        *(uint2*)(lo + off) = make_uint2(*(uint32_t*)&lp0, *(uint32_t*)&lp1);
    }
}
// synchronous bf16 B tile load (round-4 proven)
__device__ __forceinline__ void load_b_tile(char* bh, char* bl,
        const __nv_bfloat16* __restrict__ Bh, const __nv_bfloat16* __restrict__ Bl, int tid) {
#pragma unroll
    for (int i = 0; i < 8; i++) {
        int f = tid + 256 * i;
        int r = f >> 4, c8 = (f & 15) * 8;
        uint32_t off = r * RB + c8 * 2;
        *(uint4*)(bh + off) = *(const uint4*)(Bh + r * DD + c8);
        *(uint4*)(bl + off) = *(const uint4*)(Bl + r * DD + c8);
    }
}
// async bf16 B tile load
__device__ __forceinline__ void load_b_async(char* bh, char* bl,
        const __nv_bfloat16* __restrict__ Bh, const __nv_bfloat16* __restrict__ Bl, int tid) {
    uint32_t uh = smem_u32(bh), ul = smem_u32(bl);
#pragma unroll
    for (int i = 0; i < 8; i++) {
        int f = tid + 256 * i;
        int r = f >> 4, c8 = (f & 15) * 8;
        uint32_t off = r * RB + c8 * 2;
        cp16(uh + off, Bh + r * DD + c8);
        cp16(ul + off, Bl + r * DD + c8);
    }
}

// 3-term split K=128 accumulate into acc[2][8][4] (proven round-4 inner loop)
__device__ __forceinline__ void mma_accum_3term(float acc[2][8][4],
        uint32_t uAH, uint32_t uAL, uint32_t uBH, uint32_t uBL,
        uint32_t aoff, uint32_t boff) {
#pragma unroll
    for (int t = 0; t < 3; t++) {
        uint32_t ua = (t < 2) ? uAH : uAL;
        uint32_t ub = (t == 1) ? uBL : uBH;
#pragma unroll
        for (int k = 0; k < 8; k++) {
            uint32_t kb = k * 32;
            uint32_t afr[2][4], bfr[4][4];
            ldsm_x4(afr[0], ua + aoff + kb);
            ldsm_x4(afr[1], ua + aoff + kb + 16 * RB);
#pragma unroll
            for (int ni = 0; ni < 4; ni++)
                ldsm_x4(bfr[ni], ub + boff + kb + ni * 16 * RB);
#pragma unroll
            for (int mi = 0; mi < 2; mi++)
#pragma unroll
                for (int ni = 0; ni < 4; ni++) {
                    mma16816(acc[mi][ni * 2 + 0], afr[mi], &bfr[ni][0]);
                    mma16816(acc[mi][ni * 2 + 1], afr[mi], &bfr[ni][2]);
                }
        }
    }
}
__device__ __forceinline__ void zero_acc(float acc[2][8][4]) {
#pragma unroll
    for (int mi = 0; mi < 2; mi++)
#pragma unroll
        for (int n8 = 0; n8 < 8; n8++)
#pragma unroll
            for (int j = 0; j < 4; j++) acc[mi][n8][j] = 0.f;
}

// gather-sum h rows by (dst,etype) bucket into a hi/lo bf16 smem A tile
__device__ __forceinline__ void gather_rows(char* hi, char* lo, int t, int row0,
                                            int wid, int lane) {
#pragma unroll 1
    for (int rr = 0; rr < 16; rr++) {
        int r = wid * 16 + rr;
        int d = row0 + r;
        float4 a = make_float4(0.f, 0.f, 0.f, 0.f);
        if (d < NN) {
            int b = d * 4 + t;
            int i0 = g_off[b], i1 = g_off[b + 1];
            for (int i = i0; i < i1; i++) {
                const float4 v = *(const float4*)&g_h[g_gsrc[i] + lane * 4];
                a.x += v.x; a.y += v.y; a.z += v.z; a.w += v.w;
            }
        }
        __nv_bfloat16 h0 = __float2bfloat16(a.x), h1 = __float2bfloat16(a.y);
        __nv_bfloat16 h2 = __float2bfloat16(a.z), h3 = __float2bfloat16(a.w);
        __nv_bfloat16 l0 = __float2bfloat16(a.x - __bfloat162float(h0));
        __nv_bfloat16 l1 = __float2bfloat16(a.y - __bfloat162float(h1));
        __nv_bfloat16 l2 = __float2bfloat16(a.z - __bfloat162float(h2));
        __nv_bfloat16 l3 = __float2bfloat16(a.w - __bfloat162float(h3));
        __nv_bfloat162 hp0 = {h0, h1}, hp1 = {h2, h3};
        __nv_bfloat162 lp0 = {l0, l1}, lp1 = {l2, l3};
        uint32_t off = (uint32_t)(r * RB + lane * 8);
        *(uint2*)(hi + off) = make_uint2(*(uint32_t*)&hp0, *(uint32_t*)&hp1);
        *(uint2*)(lo + off) = make_uint2(*(uint32_t*)&lp0, *(uint32_t*)&lp1);
    }
}

// ---------------- fused message kernel: a = sum_t s_t @ W_t + cnt_t*b_t --
__global__ __launch_bounds__(256, 1) void msg_kernel(const float* __restrict__ bmsg) {
    extern __shared__ char smem[];
    char* sA[2][2] = {{smem, smem + AT128},
                      {smem + 2 * AT128, smem + 3 * AT128}};
    char* sBH = smem + 4 * AT128;
    char* sBL = smem + 5 * AT128;
    float* sbias = (float*)(smem + 6 * AT128);
    const int tid = threadIdx.x, wid = tid >> 5, lane = tid & 31;
    const int wm = wid & 3, wn = wid >> 2;
    const int row0 = blockIdx.x * 128;

    sbias[tid] = bmsg[tid];
    sbias[tid + 256] = bmsg[tid + 256];

    const uint32_t aoff = (uint32_t)((wm * 32 + (lane & 15)) * RB + (lane >> 4) * 16);
    const uint32_t boff = (uint32_t)((wn * 64 + ((lane >> 4) & 1) * 8 + (lane & 7)) * RB
                                     + ((lane >> 3) & 1) * 16);
    const uint32_t uBH = smem_u32(sBH), uBL = smem_u32(sBL);

    float acc[2][8][4];
    zero_acc(acc);

    // prologue: B(0) async + gather(0)
    load_b_async(sBH, sBL, g_Wt_hi, g_Wt_lo, tid);
    CP_COMMIT();
    gather_rows(sA[0][0], sA[0][1], 0, row0, wid, lane);
    CP_WAIT0();
    __syncthreads();

#pragma unroll 1
    for (int t = 0; t < 4; t++) {
        int pb = t & 1;
        mma_accum_3term(acc, smem_u32(sA[pb][0]), smem_u32(sA[pb][1]),
                        uBH, uBL, aoff, boff);
        if (t < 3) {
            __syncthreads();   // all warps done reading B(t) and A[(t-1)&1]
            load_b_async(sBH, sBL, g_Wt_hi + (t + 1) * 16384,
                         g_Wt_lo + (t + 1) * 16384, tid);
            CP_COMMIT();
            gather_rows(sA[pb ^ 1][0], sA[pb ^ 1][1], t + 1, row0, wid, lane);
            CP_WAIT0();
            __syncthreads();
        }
    }

    // epilogue: a = acc + sum_t cnt_t * b_msg[t]
#pragma unroll
    for (int mi = 0; mi < 2; mi++) {
        int r0 = row0 + wm * 32 + mi * 16 + (lane >> 2);
        float cA[4] = {0.f, 0.f, 0.f, 0.f}, cB[4] = {0.f, 0.f, 0.f, 0.f};
        if (r0 < NN) {
            int b = r0 * 4;
            int o0 = g_off[b], o1 = g_off[b + 1], o2 = g_off[b + 2];
            int o3 = g_off[b + 3], o4 = g_off[b + 4];
            cA[0] = (float)(o1 - o0); cA[1] = (float)(o2 - o1);
            cA[2] = (float)(o3 - o2); cA[3] = (float)(o4 - o3);
        }
        if (r0 + 8 < NN) {
            int b = (r0 + 8) * 4;
            int o0 = g_off[b], o1 = g_off[b + 1], o2 = g_off[b + 2];
            int o3 = g_off[b + 3], o4 = g_off[b + 4];
            cB[0] = (float)(o1 - o0); cB[1] = (float)(o2 - o1);
            cB[2] = (float)(o3 - o2); cB[3] = (float)(o4 - o3);
        }
#pragma unroll
        for (int n8 = 0; n8 < 8; n8++) {
            int col = wn * 64 + n8 * 8 + (lane & 3) * 2;
            float k0a = 0.f, k1a = 0.f, k0b = 0.f, k1b = 0.f;
#pragma unroll
            for (int t = 0; t < 4; t++) {
                float b0 = sbias[t * 128 + col], b1 = sbias[t * 128 + col + 1];
                k0a += cA[t] * b0; k1a += cA[t] * b1;
                k0b += cB[t] * b0; k1b += cB[t] * b1;
            }
            if (r0 < NN)
                *(float2*)(g_a + (size_t)r0 * DD + col) =
                    make_float2(acc[mi][n8][0] + k0a, acc[mi][n8][1] + k1a);
            if (r0 + 8 < NN)
                *(float2*)(g_a + (size_t)(r0 + 8) * DD + col) =
                    make_float2(acc[mi][n8][2] + k0b, acc[mi][n8][3] + k1b);
        }
    }
}

// ---------------- fused gates GEMM (exact round-4 version) --------------
// y=0: g_rs = a@wih_r + h@whh_r ; y=1: g_zs ; y=2: g_in = a@wih_n ; y=3: g_hn = h@whh_n
__global__ __launch_bounds__(256, 1) void gates_tc() {
    extern __shared__ char smem[];
    char* sAaH = smem;
    char* sAaL = smem + AT128;
    char* sAhH = smem + 2 * AT128;
    char* sAhL = smem + 3 * AT128;
    char* sBH  = smem + 4 * AT128;
    char* sBL  = smem + 5 * AT128;
    const int tid = threadIdx.x, wid = tid >> 5, lane = tid & 31;
    const int wm = wid & 3, wn = wid >> 2;
    const int row0 = blockIdx.x * 128;
    const int y = blockIdx.y;
    const int chunk = (y < 2) ? y : 2;

    if (y != 3) load_f32_split_tile(sAaH, sAaL, g_a, row0, NN, tid);
    if (y != 2) load_f32_split_tile(sAhH, sAhL, g_h, row0, NN, tid);
    if (y == 3) load_b_tile(sBH, sBL, g_Bhh_hi + 2 * 16384, g_Bhh_lo + 2 * 16384, tid);
    else        load_b_tile(sBH, sBL, g_Bih_hi + chunk * 16384, g_Bih_lo + chunk * 16384, tid);
    __syncthreads();

    const uint32_t aoff = (uint32_t)((wm * 32 + (lane & 15)) * RB + (lane >> 4) * 16);
    const uint32_t boff = (uint32_t)((wn * 64 + ((lane >> 4) & 1) * 8 + (lane & 7)) * RB
                                     + ((lane >> 3) & 1) * 16);
    float acc[2][8][4];
    zero_acc(acc);

    {
        uint32_t uH = (y == 3) ? smem_u32(sAhH) : smem_u32(sAaH);
        uint32_t uL = (y == 3) ? smem_u32(sAhL) : smem_u32(sAaL);
        mma_accum_3term(acc, uH, uL, smem_u32(sBH), smem_u32(sBL), aoff, boff);
    }
    if (y < 2) {
        __syncthreads();
        load_b_tile(sBH, sBL, g_Bhh_hi + chunk * 16384, g_Bhh_lo + chunk * 16384, tid);
        __syncthreads();
        mma_accum_3term(acc, smem_u32(sAhH), smem_u32(sAhL),
                        smem_u32(sBH), smem_u32(sBL), aoff, boff);
    }

    float* C = (y == 0) ? g_rs : (y == 1) ? g_zs : (y == 2) ? g_in : g_hn;
#pragma unroll
    for (int mi = 0; mi < 2; mi++) {
        int r0 = row0 + wm * 32 + mi * 16 + (lane >> 2);
#pragma unroll
        for (int n8 = 0; n8 < 8; n8++) {
            int col = wn * 64 + n8 * 8 + (lane & 3) * 2;
            if (r0 < NN)
                *(float2*)(C + (size_t)r0 * DD + col) =
                    make_float2(acc[mi][n8][0], acc[mi][n8][1]);
            if (r0 + 8 < NN)
                *(float2*)(C + (size_t)(r0 + 8) * DD + col) =
                    make_float2(acc[mi][n8][2], acc[mi][n8][3]);
        }
    }
}

// ---------------- weight prep ----------------
__global__ void prep_wmsg(const float* __restrict__ Wmsg) {
    int idx = blockIdx.x * blockDim.x + threadIdx.x;
    if (idx >= TT * DD * DD) return;
    int t = idx >> 14, rem = idx & 16383, e = rem >> 7, d = rem & 127;
    float w = Wmsg[t * 16384 + d * 128 + e];
    __nv_bfloat16 hi = __float2bfloat16(w);
    g_Wt_hi[idx] = hi;
    g_Wt_lo[idx] = __float2bfloat16(w - __bfloat162float(hi));
}
__global__ void prep_gates(const float* __restrict__ wih, const float* __restrict__ whh) {
    int idx = blockIdx.x * blockDim.x + threadIdx.x;
    if (idx >= 3 * DD * DD) return;
    int c = idx >> 7, k = idx & 127;
    float wi = wih[k * 384 + c];
    float wh = whh[k * 384 + c];
    __nv_bfloat16 hi = __float2bfloat16(wi);
    g_Bih_hi[idx] = hi;
    g_Bih_lo[idx] = __float2bfloat16(wi - __bfloat162float(hi));
    __nv_bfloat16 hh = __float2bfloat16(wh);
    g_Bhh_hi[idx] = hh;
    g_Bhh_lo[idx] = __float2bfloat16(wh - __bfloat162float(hh));
}

// ---------------- init ----------------
__global__ void init_kernel(const float* __restrict__ features) {
    int idx = blockIdx.x * blockDim.x + threadIdx.x;
    if (idx >= NN * DD) return;
    int n = idx >> 7, j = idx & 127;
    float v = (j < DIN) ? features[n * DIN + j] : 0.f;
    g_h1[idx] = v;
    g_h [idx] = v;
}

// ---------------- CSR build (keyed by dst*4+etype) ----------------
__global__ void zero_cnt_kernel() {
    int i = blockIdx.x * blockDim.x + threadIdx.x;
    if (i < NT) g_cnt[i] = 0;
}
__global__ void count_kernel(const int* __restrict__ dst, const int* __restrict__ et) {
    int e = blockIdx.x * blockDim.x + threadIdx.x;
    if (e >= EE) return;
    g_eoff[e] = atomicAdd(&g_cnt[dst[e] * 4 + et[e]], 1);
}
__global__ void scan_a_kernel() {
    __shared__ int s[1024];
    int b = blockIdx.x, t = threadIdx.x;
    int n = b * 1024 + t;
    int v = (n < NT) ? g_cnt[n] : 0;
    s[t] = v;
    __syncthreads();
    for (int d = 1; d < 1024; d <<= 1) {
        int x = (t >= d) ? s[t - d] : 0;
        __syncthreads();
        s[t] += x;
        __syncthreads();
    }
    if (n < NT) g_scan[n] = s[t] - v;
    if (t == 1023) g_part[b] = s[1023];
}
__global__ void scan_b_kernel() {
    __shared__ int s[256];
    int t = threadIdx.x;
    int v = (t < NBS) ? g_part[t] : 0;
    s[t] = v;
    __syncthreads();
    for (int d = 1; d < 256; d <<= 1) {
        int x = (t >= d) ? s[t - d] : 0;
        __syncthreads();
        s[t] += x;
        __syncthreads();
    }
    g_part2[t] = s[t] - v;
}
__global__ void scan_c_kernel() {
    int n = blockIdx.x * blockDim.x + threadIdx.x;
    if (n < NT) g_off[n] = g_scan[n] + g_part2[n >> 10];
    if (n == 0) g_off[NT] = EE;
}
__global__ void fill_kernel(const int* __restrict__ src, const int* __restrict__ dst,
                            const int* __restrict__ et) {
    int e = blockIdx.x * blockDim.x + threadIdx.x;
    if (e >= EE) return;
    int pos = g_off[dst[e] * 4 + et[e]] + g_eoff[e];
    g_gsrc[pos] = src[e] * DD;
}

// ---------------- GRU pointwise (round-4) ----------------
__global__ void gru_kernel(const float* __restrict__ bih, const float* __restrict__ bhh) {
    int idx = blockIdx.x * blockDim.x + threadIdx.x;
    if (idx >= NN * 32) return;
    int n = idx >> 5, q = idx & 31;
    int col = q * 4;
    size_t o = (size_t)n * DD + col;
    float4 rs = *(const float4*)&g_rs[o];
    float4 zs = *(const float4*)&g_zs[o];
    float4 iv = *(const float4*)&g_in[o];
    float4 hv = *(const float4*)&g_hn[o];
    float4 h  = *(const float4*)&g_h [o];
    float4 br  = *(const float4*)&bih[col];
    float4 br2 = *(const float4*)&bhh[col];
    float4 bz  = *(const float4*)&bih[128 + col];
    float4 bz2 = *(const float4*)&bhh[128 + col];
    float4 bn  = *(const float4*)&bih[256 + col];
    float4 bn2 = *(const float4*)&bhh[256 + col];
    float4 out;
    {
        float r = 1.f / (1.f + expf(-(rs.x + br.x + br2.x)));
        float z = 1.f / (1.f + expf(-(zs.x + bz.x + bz2.x)));
        float ng = tanhf(iv.x + bn.x + r * (hv.x + bn2.x));
        out.x = (1.f - z) * ng + z * h.x;
    }
    {
        float r = 1.f / (1.f + expf(-(rs.y + br.y + br2.y)));
        float z = 1.f / (1.f + expf(-(zs.y + bz.y + bz2.y)));
        float ng = tanhf(iv.y + bn.y + r * (hv.y + bn2.y));
        out.y = (1.f - z) * ng + z * h.y;
    }
    {
        float r = 1.f / (1.f + expf(-(rs.z + br.z + br2.z)));
        float z = 1.f / (1.f + expf(-(zs.z + bz.z + bz2.z)));
        float ng = tanhf(iv.z + bn.z + r * (hv.z + bn2.z));
        out.z = (1.f - z) * ng + z * h.z;
    }
    {
        float r = 1.f / (1.f + expf(-(rs.w + br.w + br2.w)));
        float z = 1.f / (1.f + expf(-(zs.w + bz.w + bz2.w)));
        float ng = tanhf(iv.w + bn.w + r * (hv.w + bn2.w));
        out.w = (1.f - z) * ng + z * h.w;
    }
    *(float4*)&g_h[o] = out;
}

// ---------------- pooling + classifier ----------------
__global__ void zero_feats_kernel() {
    int i = blockIdx.x * blockDim.x + threadIdx.x;
    if (i < BG * DD) g_feats[i] = 0.f;
}
__global__ void pool_kernel(const int* __restrict__ n2g) {
    int n0 = blockIdx.x * 64;
    int j  = threadIdx.x;
    if (n0 >= NN) return;
    float acc = 0.f;
    int cur = n2g[n0];
    for (int i = 0; i < 64; i++) {
        int n = n0 + i;
        if (n >= NN) break;
        int g = n2g[n];
        if (g != cur) {
            atomicAdd(&g_feats[cur * DD + j], acc);
            acc = 0.f; cur = g;
        }
        acc += g_h[n * DD + j] + g_h1[n * DD + j];
    }
    atomicAdd(&g_feats[cur * DD + j], acc);
}
__global__ void cls_kernel(const float* __restrict__ Wc,
                           const float* __restrict__ bc,
                           float* __restrict__ out) {
    int tid = threadIdx.x;
    if (tid >= BG * 2) return;
    int g = tid >> 1, c = tid & 1;
    float s = bc[c];
#pragma unroll 8
    for (int k = 0; k < DD; k++) s += g_feats[g * DD + k] * Wc[k * 2 + c];
    out[g * 2 + c] = s;
}

// ---------------- launch ----------------
extern "C" void kernel_launch(void* const* d_in, const int* in_sizes, int n_in,
                              void* d_out, int out_size) {
    const float* features = (const float*)d_in[0];
    const int*   src      = (const int*)  d_in[1];
    const int*   dst      = (const int*)  d_in[2];
    const int*   etype    = (const int*)  d_in[3];
    const int*   n2g      = (const int*)  d_in[4];
    const float* W_msg    = (const float*)d_in[5];
    const float* b_msg    = (const float*)d_in[6];
    const float* w_ih     = (const float*)d_in[7];
    const float* b_ih     = (const float*)d_in[8];
    const float* w_hh     = (const float*)d_in[9];
    const float* b_hh     = (const float*)d_in[10];
    const float* W_cls    = (const float*)d_in[11];
    const float* b_cls    = (const float*)d_in[12];
    float* out = (float*)d_out;

    static int smem_set = 0;
    if (!smem_set) {
        cudaFuncSetAttribute(msg_kernel,
                             cudaFuncAttributeMaxDynamicSharedMemorySize, MS_SMEM);
        cudaFuncSetAttribute(gates_tc,
                             cudaFuncAttributeMaxDynamicSharedMemorySize, G6SMEM);
        smem_set = 1;
    }

    // prologue: weights, init, CSR build by (dst, etype)
    prep_wmsg<<<(TT * DD * DD + 255) / 256, 256>>>(W_msg);
    prep_gates<<<(3 * DD * DD + 255) / 256, 256>>>(w_ih, w_hh);
    init_kernel<<<(NN * DD + 255) / 256, 256>>>(features);
    zero_cnt_kernel<<<(NT + 255) / 256, 256>>>();
    count_kernel<<<(EE + 255) / 256, 256>>>(dst, etype);
    scan_a_kernel<<<NBS, 1024>>>();
    scan_b_kernel<<<1, 256>>>();
    scan_c_kernel<<<(NT + 255) / 256, 256>>>();
    fill_kernel<<<(EE + 255) / 256, 256>>>(src, dst, etype);

    for (int s = 0; s < NSTEPS; s++) {
        msg_kernel<<<RTILES, 256, MS_SMEM>>>(b_msg);
        gates_tc<<<dim3(RTILES, 4), 256, G6SMEM>>>();
        gru_kernel<<<(NN * 32 + 255) / 256, 256>>>(b_ih, b_hh);
    }

    zero_feats_kernel<<<(BG * DD + 255) / 256, 256>>>();
    pool_kernel<<<(NN + 63) / 64, 128>>>(n2g);
    cls_kernel<<<1, 128>>>(W_cls, b_cls, out);
}

// round 9
// speedup vs baseline: 1.2034x; 1.2034x over previous
#include <cuda_runtime.h>
#include <cuda_bf16.h>
#include <cstdint>

#define NN 50000
#define EE 400000
#define TT 4
#define DIN 64
#define DD 128
#define BG 64
#define NSTEPS 8
#define RTILES ((NN + 127) / 128)   // 391
#define NB1 ((NN + 255) / 256)      // 196

// ---------------- device scratch ----------------
__device__ float g_h [NN * DD];
__device__ float g_h1[NN * DD];
__device__ float g_t [NN * TT * DD];
__device__ float g_a [NN * DD];
__device__ float g_rs[NN * DD];
__device__ float g_zs[NN * DD];
__device__ float g_in[NN * DD];
__device__ float g_hn[NN * DD];
__device__ float g_feats[BG * DD];
// CSR by dst
__device__ int g_cnt [NN];
__device__ int g_scan[NN];
__device__ int g_off [NN + 1];
__device__ int g_part [256];
__device__ int g_part2[256];
__device__ int g_eoff[EE];
__device__ int g_gsrc[EE];               // payload: src*512 + etype*128
// prepped bf16 hi/lo weights, B layout [col][k]
__device__ __nv_bfloat16 g_Wt_hi [TT * DD * DD];
__device__ __nv_bfloat16 g_Wt_lo [TT * DD * DD];
__device__ __nv_bfloat16 g_Bih_hi[3 * DD * DD];
__device__ __nv_bfloat16 g_Bih_lo[3 * DD * DD];
__device__ __nv_bfloat16 g_Bhh_hi[3 * DD * DD];
__device__ __nv_bfloat16 g_Bhh_lo[3 * DD * DD];

// ---------------- helpers ----------------
__device__ __forceinline__ uint32_t smem_u32(const void* p) {
    return (uint32_t)__cvta_generic_to_shared(p);
}
__device__ __forceinline__ void ldsm_x4(uint32_t* r, uint32_t addr) {
    asm volatile("ldmatrix.sync.aligned.m8n8.x4.shared.b16 {%0,%1,%2,%3}, [%4];"
                 : "=r"(r[0]), "=r"(r[1]), "=r"(r[2]), "=r"(r[3]) : "r"(addr));
}
__device__ __forceinline__ void mma16816(float* d, const uint32_t* a, const uint32_t* b) {
    asm volatile(
        "mma.sync.aligned.m16n8k16.row.col.f32.bf16.bf16.f32 "
        "{%0,%1,%2,%3}, {%4,%5,%6,%7}, {%8,%9}, {%0,%1,%2,%3};"
        : "+f"(d[0]), "+f"(d[1]), "+f"(d[2]), "+f"(d[3])
        : "r"(a[0]), "r"(a[1]), "r"(a[2]), "r"(a[3]), "r"(b[0]), "r"(b[1]));
}

#define TROW 136
#define RB   (TROW * 2)            // 272
#define AT128 (128 * RB)           // 34816
#define GSMEM (4 * AT128)          // 139264

// fp32 -> hi/lo bf16 split (128 rows)
__device__ __forceinline__ void load_f32_split_tile(char* hi, char* lo,
        const float* __restrict__ src, int row0, int tid) {
#pragma unroll
    for (int i = 0; i < 16; i++) {
        int f = tid + 256 * i;
        int r = f >> 5, c4 = (f & 31) * 4;
        int gr = row0 + r;
        float4 v = make_float4(0.f, 0.f, 0.f, 0.f);
        if (gr < NN) v = *(const float4*)(src + (size_t)gr * DD + c4);
        __nv_bfloat16 h0 = __float2bfloat16(v.x), h1 = __float2bfloat16(v.y);
        __nv_bfloat16 h2 = __float2bfloat16(v.z), h3 = __float2bfloat16(v.w);
        __nv_bfloat16 l0 = __float2bfloat16(v.x - __bfloat162float(h0));
        __nv_bfloat16 l1 = __float2bfloat16(v.y - __bfloat162float(h1));
        __nv_bfloat16 l2 = __float2bfloat16(v.z - __bfloat162float(h2));
        __nv_bfloat16 l3 = __float2bfloat16(v.w - __bfloat162float(h3));
        __nv_bfloat162 hp0 = {h0, h1}, hp1 = {h2, h3};
        __nv_bfloat162 lp0 = {l0, l1}, lp1 = {l2, l3};
        uint32_t off = r * RB + c4 * 2;
        *(uint2*)(hi + off) = make_uint2(*(uint32_t*)&hp0, *(uint32_t*)&hp1);
        *(uint2*)(lo + off) = make_uint2(*(uint32_t*)&lp0, *(uint32_t*)&lp1);
    }
}
__device__ __forceinline__ void load_b_tile(char* bh, char* bl,
        const __nv_bfloat16* __restrict__ Bh, const __nv_bfloat16* __restrict__ Bl, int tid) {
#pragma unroll
    for (int i = 0; i < 8; i++) {
        int f = tid + 256 * i;
        int r = f >> 4, c8 = (f & 15) * 8;
        uint32_t off = r * RB + c8 * 2;
        *(uint4*)(bh + off) = *(const uint4*)(Bh + r * DD + c8);
        *(uint4*)(bl + off) = *(const uint4*)(Bl + r * DD + c8);
    }
}

// 3-term split K=128 accumulate into acc[2][8][4] (proven round-4 inner loop)
__device__ __forceinline__ void mma_accum_3term(float acc[2][8][4],
        uint32_t uAH, uint32_t uAL, uint32_t uBH, uint32_t uBL,
        uint32_t aoff, uint32_t boff) {
#pragma unroll
    for (int t = 0; t < 3; t++) {
        uint32_t ua = (t < 2) ? uAH : uAL;
        uint32_t ub = (t == 1) ? uBL : uBH;
#pragma unroll
        for (int k = 0; k < 8; k++) {
            uint32_t kb = k * 32;
            uint32_t afr[2][4], bfr[4][4];
            ldsm_x4(afr[0], ua + aoff + kb);
            ldsm_x4(afr[1], ua + aoff + kb + 16 * RB);
#pragma unroll
            for (int ni = 0; ni < 4; ni++)
                ldsm_x4(bfr[ni], ub + boff + kb + ni * 16 * RB);
#pragma unroll
            for (int mi = 0; mi < 2; mi++)
#pragma unroll
                for (int ni = 0; ni < 4; ni++) {
                    mma16816(acc[mi][ni * 2 + 0], afr[mi], &bfr[ni][0]);
                    mma16816(acc[mi][ni * 2 + 1], afr[mi], &bfr[ni][2]);
                }
        }
    }
}
__device__ __forceinline__ void zero_acc(float acc[2][8][4]) {
#pragma unroll
    for (int mi = 0; mi < 2; mi++)
#pragma unroll
        for (int n8 = 0; n8 < 8; n8++)
#pragma unroll
            for (int j = 0; j < 4; j++) acc[mi][n8][j] = 0.f;
}

// ---------------- transform GEMM (round-4 gemm3, grid (391,4)) ----------
__global__ __launch_bounds__(256, 1) void transform_tc(const float* __restrict__ bias) {
    extern __shared__ char smem[];
    char* sAH = smem;
    char* sAL = smem + AT128;
    char* sBH = smem + 2 * AT128;
    char* sBL = smem + 3 * AT128;
    const int tid = threadIdx.x, wid = tid >> 5, lane = tid & 31;
    const int wm = wid & 3, wn = wid >> 2;
    const int row0 = blockIdx.x * 128;
    const int tt = blockIdx.y;

    load_f32_split_tile(sAH, sAL, g_h, row0, tid);
    load_b_tile(sBH, sBL, g_Wt_hi + tt * 16384, g_Wt_lo + tt * 16384, tid);
    __syncthreads();

    const uint32_t aoff = (uint32_t)((wm * 32 + (lane & 15)) * RB + (lane >> 4) * 16);
    const uint32_t boff = (uint32_t)((wn * 64 + ((lane >> 4) & 1) * 8 + (lane & 7)) * RB
                                     + ((lane >> 3) & 1) * 16);
    float acc[2][8][4];
    zero_acc(acc);
    mma_accum_3term(acc, smem_u32(sAH), smem_u32(sAL),
                    smem_u32(sBH), smem_u32(sBL), aoff, boff);

#pragma unroll
    for (int mi = 0; mi < 2; mi++) {
        int r0 = row0 + wm * 32 + mi * 16 + (lane >> 2);
#pragma unroll
        for (int n8 = 0; n8 < 8; n8++) {
            int col = wn * 64 + n8 * 8 + (lane & 3) * 2;
            float b0 = bias[tt * 128 + col], b1 = bias[tt * 128 + col + 1];
            if (r0 < NN)
                *(float2*)(g_t + (size_t)r0 * 512 + tt * 128 + col) =
                    make_float2(acc[mi][n8][0] + b0, acc[mi][n8][1] + b1);
            if (r0 + 8 < NN)
                *(float2*)(g_t + (size_t)(r0 + 8) * 512 + tt * 128 + col) =
                    make_float2(acc[mi][n8][2] + b0, acc[mi][n8][3] + b1);
        }
    }
}

// ---------------- gh3: h @ whh_ck ; ck<2 writes rs/zs, ck=2 writes hn ---
__global__ __launch_bounds__(256, 1) void gh3_kernel() {
    extern __shared__ char smem[];
    char* sAH = smem;
    char* sAL = smem + AT128;
    char* sBH = smem + 2 * AT128;
    char* sBL = smem + 3 * AT128;
    const int tid = threadIdx.x, wid = tid >> 5, lane = tid & 31;
    const int wm = wid & 3, wn = wid >> 2;
    const int row0 = blockIdx.x * 128;
    const int ck = blockIdx.y;

    load_f32_split_tile(sAH, sAL, g_h, row0, tid);
    load_b_tile(sBH, sBL, g_Bhh_hi + ck * 16384, g_Bhh_lo + ck * 16384, tid);
    __syncthreads();

    const uint32_t aoff = (uint32_t)((wm * 32 + (lane & 15)) * RB + (lane >> 4) * 16);
    const uint32_t boff = (uint32_t)((wn * 64 + ((lane >> 4) & 1) * 8 + (lane & 7)) * RB
                                     + ((lane >> 3) & 1) * 16);
    float acc[2][8][4];
    zero_acc(acc);
    mma_accum_3term(acc, smem_u32(sAH), smem_u32(sAL),
                    smem_u32(sBH), smem_u32(sBL), aoff, boff);

    float* C = (ck == 0) ? g_rs : (ck == 1) ? g_zs : g_hn;
#pragma unroll
    for (int mi = 0; mi < 2; mi++) {
        int r0 = row0 + wm * 32 + mi * 16 + (lane >> 2);
#pragma unroll
        for (int n8 = 0; n8 < 8; n8++) {
            int col = wn * 64 + n8 * 8 + (lane & 3) * 2;
            if (r0 < NN)
                *(float2*)(C + (size_t)r0 * DD + col) =
                    make_float2(acc[mi][n8][0], acc[mi][n8][1]);
            if (r0 + 8 < NN)
                *(float2*)(C + (size_t)(r0 + 8) * DD + col) =
                    make_float2(acc[mi][n8][2], acc[mi][n8][3]);
        }
    }
}

// ---------------- gi3: a @ wih_ck ; ck<2 RMW-adds rs/zs, ck=2 writes in -
__global__ __launch_bounds__(256, 1) void gi3_kernel() {
    extern __shared__ char smem[];
    char* sAH = smem;
    char* sAL = smem + AT128;
    char* sBH = smem + 2 * AT128;
    char* sBL = smem + 3 * AT128;
    const int tid = threadIdx.x, wid = tid >> 5, lane = tid & 31;
    const int wm = wid & 3, wn = wid >> 2;
    const int row0 = blockIdx.x * 128;
    const int ck = blockIdx.y;

    load_f32_split_tile(sAH, sAL, g_a, row0, tid);
    load_b_tile(sBH, sBL, g_Bih_hi + ck * 16384, g_Bih_lo + ck * 16384, tid);
    __syncthreads();

    const uint32_t aoff = (uint32_t)((wm * 32 + (lane & 15)) * RB + (lane >> 4) * 16);
    const uint32_t boff = (uint32_t)((wn * 64 + ((lane >> 4) & 1) * 8 + (lane & 7)) * RB
                                     + ((lane >> 3) & 1) * 16);
    float acc[2][8][4];
    zero_acc(acc);
    mma_accum_3term(acc, smem_u32(sAH), smem_u32(sAL),
                    smem_u32(sBH), smem_u32(sBL), aoff, boff);

#pragma unroll
    for (int mi = 0; mi < 2; mi++) {
        int r0 = row0 + wm * 32 + mi * 16 + (lane >> 2);
#pragma unroll
        for (int n8 = 0; n8 < 8; n8++) {
            int col = wn * 64 + n8 * 8 + (lane & 3) * 2;
            if (ck < 2) {
                float* C = (ck == 0) ? g_rs : g_zs;
                if (r0 < NN) {
                    float2 o = *(float2*)(C + (size_t)r0 * DD + col);
                    *(float2*)(C + (size_t)r0 * DD + col) =
                        make_float2(o.x + acc[mi][n8][0], o.y + acc[mi][n8][1]);
                }
                if (r0 + 8 < NN) {
                    float2 o = *(float2*)(C + (size_t)(r0 + 8) * DD + col);
                    *(float2*)(C + (size_t)(r0 + 8) * DD + col) =
                        make_float2(o.x + acc[mi][n8][2], o.y + acc[mi][n8][3]);
                }
            } else {
                if (r0 < NN)
                    *(float2*)(g_in + (size_t)r0 * DD + col) =
                        make_float2(acc[mi][n8][0], acc[mi][n8][1]);
                if (r0 + 8 < NN)
                    *(float2*)(g_in + (size_t)(r0 + 8) * DD + col) =
                        make_float2(acc[mi][n8][2], acc[mi][n8][3]);
            }
        }
    }
}

// ---------------- weight prep ----------------
__global__ void prep_wmsg(const float* __restrict__ Wmsg) {
    int idx = blockIdx.x * blockDim.x + threadIdx.x;
    if (idx >= TT * DD * DD) return;
    int t = idx >> 14, rem = idx & 16383, e = rem >> 7, d = rem & 127;
    float w = Wmsg[t * 16384 + d * 128 + e];
    __nv_bfloat16 hi = __float2bfloat16(w);
    g_Wt_hi[idx] = hi;
    g_Wt_lo[idx] = __float2bfloat16(w - __bfloat162float(hi));
}
__global__ void prep_gates(const float* __restrict__ wih, const float* __restrict__ whh) {
    int idx = blockIdx.x * blockDim.x + threadIdx.x;
    if (idx >= 3 * DD * DD) return;
    int c = idx >> 7, k = idx & 127;
    float wi = wih[k * 384 + c];
    float wh = whh[k * 384 + c];
    __nv_bfloat16 hi = __float2bfloat16(wi);
    g_Bih_hi[idx] = hi;
    g_Bih_lo[idx] = __float2bfloat16(wi - __bfloat162float(hi));
    __nv_bfloat16 hh = __float2bfloat16(wh);
    g_Bhh_hi[idx] = hh;
    g_Bhh_lo[idx] = __float2bfloat16(wh - __bfloat162float(hh));
}

// ---------------- init ----------------
__global__ void init_kernel(const float* __restrict__ features) {
    int idx = blockIdx.x * blockDim.x + threadIdx.x;
    if (idx >= NN * DD) return;
    int n = idx >> 7, j = idx & 127;
    float v = (j < DIN) ? features[n * DIN + j] : 0.f;
    g_h1[idx] = v;
    g_h [idx] = v;
}

// ---------------- CSR build (by dst) ----------------
__global__ void zero_cnt_kernel() {
    int i = blockIdx.x * blockDim.x + threadIdx.x;
    if (i < NN) g_cnt[i] = 0;
}
__global__ void count_kernel(const int* __restrict__ dst) {
    int e = blockIdx.x * blockDim.x + threadIdx.x;
    if (e >= EE) return;
    g_eoff[e] = atomicAdd(&g_cnt[dst[e]], 1);
}
__global__ void scan_a_kernel() {
    __shared__ int s[256];
    int b = blockIdx.x, t = threadIdx.x;
    int n = b * 256 + t;
    int v = (n < NN) ? g_cnt[n] : 0;
    s[t] = v;
    __syncthreads();
    for (int d = 1; d < 256; d <<= 1) {
        int x = (t >= d) ? s[t - d] : 0;
        __syncthreads();
        s[t] += x;
        __syncthreads();
    }
    if (n < NN) g_scan[n] = s[t] - v;
    if (t == 255) g_part[b] = s[255];
}
__global__ void scan_b_kernel() {
    __shared__ int s[256];
    int t = threadIdx.x;
    int v = (t < NB1) ? g_part[t] : 0;
    s[t] = v;
    __syncthreads();
    for (int d = 1; d < 256; d <<= 1) {
        int x = (t >= d) ? s[t - d] : 0;
        __syncthreads();
        s[t] += x;
        __syncthreads();
    }
    g_part2[t] = s[t] - v;
}
__global__ void scan_c_kernel() {
    int n = blockIdx.x * blockDim.x + threadIdx.x;
    if (n < NN) g_off[n] = g_scan[n] + g_part2[n >> 8];
    if (n == 0) g_off[NN] = EE;
}
__global__ void fill_kernel(const int* __restrict__ src, const int* __restrict__ dst,
                            const int* __restrict__ et) {
    int e = blockIdx.x * blockDim.x + threadIdx.x;
    if (e >= EE) return;
    int pos = g_off[dst[e]] + g_eoff[e];
    g_gsrc[pos] = src[e] * 512 + et[e] * 128;
}

// ---------------- gather ----------------
__global__ __launch_bounds__(256) void gather_kernel() {
    int w = blockIdx.x * 8 + (threadIdx.x >> 5);
    if (w >= NN) return;
    int lane = threadIdx.x & 31;
    int b0 = g_off[w], b1 = g_off[w + 1];
    float4 acc = make_float4(0.f, 0.f, 0.f, 0.f);
    for (int i = b0; i < b1; i++) {
        int so = g_gsrc[i];
        float4 v = *(const float4*)&g_t[so + lane * 4];
        acc.x += v.x; acc.y += v.y; acc.z += v.z; acc.w += v.w;
    }
    *(float4*)&g_a[w * DD + lane * 4] = acc;
}

// ---------------- GRU pointwise ----------------
__global__ void gru_kernel(const float* __restrict__ bih, const float* __restrict__ bhh) {
    int idx = blockIdx.x * blockDim.x + threadIdx.x;
    if (idx >= NN * 32) return;
    int n = idx >> 5, q = idx & 31;
    int col = q * 4;
    size_t o = (size_t)n * DD + col;
    float4 rs = *(const float4*)&g_rs[o];
    float4 zs = *(const float4*)&g_zs[o];
    float4 iv = *(const float4*)&g_in[o];
    float4 hv = *(const float4*)&g_hn[o];
    float4 h  = *(const float4*)&g_h [o];
    float4 br  = *(const float4*)&bih[col];
    float4 br2 = *(const float4*)&bhh[col];
    float4 bz  = *(const float4*)&bih[128 + col];
    float4 bz2 = *(const float4*)&bhh[128 + col];
    float4 bn  = *(const float4*)&bih[256 + col];
    float4 bn2 = *(const float4*)&bhh[256 + col];
    float4 out;
    {
        float r = 1.f / (1.f + expf(-(rs.x + br.x + br2.x)));
        float z = 1.f / (1.f + expf(-(zs.x + bz.x + bz2.x)));
        float ng = tanhf(iv.x + bn.x + r * (hv.x + bn2.x));
        out.x = (1.f - z) * ng + z * h.x;
    }
    {
        float r = 1.f / (1.f + expf(-(rs.y + br.y + br2.y)));
        float z = 1.f / (1.f + expf(-(zs.y + bz.y + bz2.y)));
        float ng = tanhf(iv.y + bn.y + r * (hv.y + bn2.y));
        out.y = (1.f - z) * ng + z * h.y;
    }
    {
        float r = 1.f / (1.f + expf(-(rs.z + br.z + br2.z)));
        float z = 1.f / (1.f + expf(-(zs.z + bz.z + bz2.z)));
        float ng = tanhf(iv.z + bn.z + r * (hv.z + bn2.z));
        out.z = (1.f - z) * ng + z * h.z;
    }
    {
        float r = 1.f / (1.f + expf(-(rs.w + br.w + br2.w)));
        float z = 1.f / (1.f + expf(-(zs.w + bz.w + bz2.w)));
        float ng = tanhf(iv.w + bn.w + r * (hv.w + bn2.w));
        out.w = (1.f - z) * ng + z * h.w;
    }
    *(float4*)&g_h[o] = out;
}

// ---------------- pooling + classifier ----------------
__global__ void zero_feats_kernel() {
    int i = blockIdx.x * blockDim.x + threadIdx.x;
    if (i < BG * DD) g_feats[i] = 0.f;
}
__global__ void pool_kernel(const int* __restrict__ n2g) {
    int n0 = blockIdx.x * 64;
    int j  = threadIdx.x;
    if (n0 >= NN) return;
    float acc = 0.f;
    int cur = n2g[n0];
    for (int i = 0; i < 64; i++) {
        int n = n0 + i;
        if (n >= NN) break;
        int g = n2g[n];
        if (g != cur) {
            atomicAdd(&g_feats[cur * DD + j], acc);
            acc = 0.f; cur = g;
        }
        acc += g_h[n * DD + j] + g_h1[n * DD + j];
    }
    atomicAdd(&g_feats[cur * DD + j], acc);
}
__global__ void cls_kernel(const float* __restrict__ Wc,
                           const float* __restrict__ bc,
                           float* __restrict__ out) {
    int tid = threadIdx.x;
    if (tid >= BG * 2) return;
    int g = tid >> 1, c = tid & 1;
    float s = bc[c];
#pragma unroll 8
    for (int k = 0; k < DD; k++) s += g_feats[g * DD + k] * Wc[k * 2 + c];
    out[g * 2 + c] = s;
}

// ---------------- launch ----------------
extern "C" void kernel_launch(void* const* d_in, const int* in_sizes, int n_in,
                              void* d_out, int out_size) {
    const float* features = (const float*)d_in[0];
    const int*   src      = (const int*)  d_in[1];
    const int*   dst      = (const int*)  d_in[2];
    const int*   etype    = (const int*)  d_in[3];
    const int*   n2g      = (const int*)  d_in[4];
    const float* W_msg    = (const float*)d_in[5];
    const float* b_msg    = (const float*)d_in[6];
    const float* w_ih     = (const float*)d_in[7];
    const float* b_ih     = (const float*)d_in[8];
    const float* w_hh     = (const float*)d_in[9];
    const float* b_hh     = (const float*)d_in[10];
    const float* W_cls    = (const float*)d_in[11];
    const float* b_cls    = (const float*)d_in[12];
    float* out = (float*)d_out;

    static cudaStream_t s2 = nullptr;
    static cudaEvent_t evFork = nullptr, evJoin = nullptr;
    static int inited = 0;
    if (!inited) {
        cudaFuncSetAttribute(transform_tc,
                             cudaFuncAttributeMaxDynamicSharedMemorySize, GSMEM);
        cudaFuncSetAttribute(gi3_kernel,
                             cudaFuncAttributeMaxDynamicSharedMemorySize, GSMEM);
        cudaFuncSetAttribute(gh3_kernel,
                             cudaFuncAttributeMaxDynamicSharedMemorySize, GSMEM);
        cudaStreamCreateWithFlags(&s2, cudaStreamNonBlocking);
        cudaEventCreateWithFlags(&evFork, cudaEventDisableTiming);
        cudaEventCreateWithFlags(&evJoin, cudaEventDisableTiming);
        inited = 1;
    }

    // prologue (main stream)
    prep_wmsg<<<(TT * DD * DD + 255) / 256, 256>>>(W_msg);
    prep_gates<<<(3 * DD * DD + 255) / 256, 256>>>(w_ih, w_hh);
    init_kernel<<<(NN * DD + 255) / 256, 256>>>(features);
    zero_cnt_kernel<<<(NN + 255) / 256, 256>>>();
    count_kernel<<<(EE + 255) / 256, 256>>>(dst);
    scan_a_kernel<<<NB1, 256>>>();
    scan_b_kernel<<<1, 256>>>();
    scan_c_kernel<<<(NN + 255) / 256, 256>>>();
    fill_kernel<<<(EE + 255) / 256, 256>>>(src, dst, etype);

    for (int s = 0; s < NSTEPS; s++) {
        // fork: h-side gate GEMMs run concurrently with transform+gather
        cudaEventRecord(evFork, 0);
        cudaStreamWaitEvent(s2, evFork, 0);
        gh3_kernel<<<dim3(RTILES, 3), 256, GSMEM, s2>>>();
        cudaEventRecord(evJoin, s2);

        transform_tc<<<dim3(RTILES, TT), 256, GSMEM>>>(b_msg);
        gather_kernel<<<(NN + 7) / 8, 256>>>();

        // join: gi3 RMW-adds into rs/zs written by gh3
        cudaStreamWaitEvent(0, evJoin, 0);
        gi3_kernel<<<dim3(RTILES, 3), 256, GSMEM>>>();
        gru_kernel<<<(NN * 32 + 255) / 256, 256>>>(b_ih, b_hh);
    }

    zero_feats_kernel<<<(BG * DD + 255) / 256, 256>>>();
    pool_kernel<<<(NN + 63) / 64, 128>>>(n2g);
    cls_kernel<<<1, 128>>>(W_cls, b_cls, out);
}

// round 10
// speedup vs baseline: 1.3194x; 1.0965x over previous
#include <cuda_runtime.h>
#include <cuda_bf16.h>
#include <cstdint>

#define NN 50000
#define EE 400000
#define TT 4
#define DIN 64
#define DD 128
#define BG 64
#define NSTEPS 8
#define RTILES ((NN + 127) / 128)   // 391
#define TPB 37                      // persistent transform blocks per type
#define NB1 ((NN + 255) / 256)      // 196

// ---------------- device scratch ----------------
__device__ float g_h1[NN * DD];                       // residual (fp32)
__device__ float g_t [NN * TT * DD];                  // messages (fp32)
__device__ float g_rs[NN * DD];
__device__ float g_zs[NN * DD];
__device__ float g_in[NN * DD];
__device__ float g_hn[NN * DD];
__device__ float g_feats[BG * DD];
// state kept pre-split as bf16 hi/lo (padded by one tile for OOB cp.async)
__device__ __nv_bfloat16 g_hh[(NN + 128) * DD];
__device__ __nv_bfloat16 g_hl[(NN + 128) * DD];
__device__ __nv_bfloat16 g_ah[(NN + 128) * DD];
__device__ __nv_bfloat16 g_al[(NN + 128) * DD];
// CSR by dst
__device__ int g_cnt [NN];
__device__ int g_scan[NN];
__device__ int g_off [NN + 1];
__device__ int g_part [256];
__device__ int g_part2[256];
__device__ int g_eoff[EE];
__device__ int g_gsrc[EE];               // payload: src*512 + etype*128
// prepped bf16 hi/lo weights, B layout [col][k]
__device__ __nv_bfloat16 g_Wt_hi [TT * DD * DD];
__device__ __nv_bfloat16 g_Wt_lo [TT * DD * DD];
__device__ __nv_bfloat16 g_Bih_hi[3 * DD * DD];
__device__ __nv_bfloat16 g_Bih_lo[3 * DD * DD];
__device__ __nv_bfloat16 g_Bhh_hi[3 * DD * DD];
__device__ __nv_bfloat16 g_Bhh_lo[3 * DD * DD];

// ---------------- helpers ----------------
__device__ __forceinline__ uint32_t smem_u32(const void* p) {
    return (uint32_t)__cvta_generic_to_shared(p);
}
__device__ __forceinline__ void ldsm_x4(uint32_t* r, uint32_t addr) {
    asm volatile("ldmatrix.sync.aligned.m8n8.x4.shared.b16 {%0,%1,%2,%3}, [%4];"
                 : "=r"(r[0]), "=r"(r[1]), "=r"(r[2]), "=r"(r[3]) : "r"(addr));
}
__device__ __forceinline__ void mma16816(float* d, const uint32_t* a, const uint32_t* b) {
    asm volatile(
        "mma.sync.aligned.m16n8k16.row.col.f32.bf16.bf16.f32 "
        "{%0,%1,%2,%3}, {%4,%5,%6,%7}, {%8,%9}, {%0,%1,%2,%3};"
        : "+f"(d[0]), "+f"(d[1]), "+f"(d[2]), "+f"(d[3])
        : "r"(a[0]), "r"(a[1]), "r"(a[2]), "r"(a[3]), "r"(b[0]), "r"(b[1]));
}
__device__ __forceinline__ void cp16(uint32_t dst, const void* src) {
    asm volatile("cp.async.cg.shared.global [%0], [%1], 16;" :: "r"(dst), "l"(src));
}
#define CP_COMMIT() asm volatile("cp.async.commit_group;" ::: "memory")
#define CP_WAIT(n)  asm volatile("cp.async.wait_group %0;" :: "n"(n) : "memory")

#define TROW 136
#define RB   (TROW * 2)            // 272
#define AT128 (128 * RB)           // 34816
#define SM6   (6 * AT128)          // 208896

// async copy of a 128x128 bf16 tile-pair (hi + lo), row-major [128][128] source
__device__ __forceinline__ void tile_async(char* bh, char* bl,
        const __nv_bfloat16* __restrict__ Bh, const __nv_bfloat16* __restrict__ Bl, int tid) {
    uint32_t uh = smem_u32(bh), ul = smem_u32(bl);
#pragma unroll
    for (int i = 0; i < 8; i++) {
        int f = tid + 256 * i;
        int r = f >> 4, c8 = (f & 15) * 8;
        uint32_t off = r * RB + c8 * 2;
        cp16(uh + off, Bh + (size_t)r * DD + c8);
        cp16(ul + off, Bl + (size_t)r * DD + c8);
    }
}

// 3-term split K=128 accumulate into acc[2][8][4] (proven round-4 inner loop)
__device__ __forceinline__ void mma_accum_3term(float acc[2][8][4],
        uint32_t uAH, uint32_t uAL, uint32_t uBH, uint32_t uBL,
        uint32_t aoff, uint32_t boff) {
#pragma unroll
    for (int t = 0; t < 3; t++) {
        uint32_t ua = (t < 2) ? uAH : uAL;
        uint32_t ub = (t == 1) ? uBL : uBH;
#pragma unroll
        for (int k = 0; k < 8; k++) {
            uint32_t kb = k * 32;
            uint32_t afr[2][4], bfr[4][4];
            ldsm_x4(afr[0], ua + aoff + kb);
            ldsm_x4(afr[1], ua + aoff + kb + 16 * RB);
#pragma unroll
            for (int ni = 0; ni < 4; ni++)
                ldsm_x4(bfr[ni], ub + boff + kb + ni * 16 * RB);
#pragma unroll
            for (int mi = 0; mi < 2; mi++)
#pragma unroll
                for (int ni = 0; ni < 4; ni++) {
                    mma16816(acc[mi][ni * 2 + 0], afr[mi], &bfr[ni][0]);
                    mma16816(acc[mi][ni * 2 + 1], afr[mi], &bfr[ni][2]);
                }
        }
    }
}
__device__ __forceinline__ void zero_acc(float acc[2][8][4]) {
#pragma unroll
    for (int mi = 0; mi < 2; mi++)
#pragma unroll
        for (int n8 = 0; n8 < 8; n8++)
#pragma unroll
            for (int j = 0; j < 4; j++) acc[mi][n8][j] = 0.f;
}

// split a float into bf16 hi/lo
__device__ __forceinline__ void split2(float v, __nv_bfloat16& h, __nv_bfloat16& l) {
    h = __float2bfloat16(v);
    l = __float2bfloat16(v - __bfloat162float(h));
}

// ---------------- transform: persistent, grid (37, 4) ----------------
// g_t[:, tt*128:+128] = h @ Wmsg[tt]^T + bmsg[tt]; A double-buffered cp.async
__global__ __launch_bounds__(256, 1) void transform_tc(const float* __restrict__ bias) {
    extern __shared__ char smem[];
    char* sA0H = smem;
    char* sA0L = smem + AT128;
    char* sA1H = smem + 2 * AT128;
    char* sA1L = smem + 3 * AT128;
    char* sBH  = smem + 4 * AT128;
    char* sBL  = smem + 5 * AT128;
    const int tid = threadIdx.x, wid = tid >> 5, lane = tid & 31;
    const int wm = wid & 3, wn = wid >> 2;
    const int x = blockIdx.x, tt = blockIdx.y;

    // group 0: B + first A tile
    tile_async(sBH, sBL, g_Wt_hi + tt * 16384, g_Wt_lo + tt * 16384, tid);
    tile_async(sA0H, sA0L, g_hh + (size_t)x * 128 * DD, g_hl + (size_t)x * 128 * DD, tid);
    CP_COMMIT();

    const uint32_t aoff = (uint32_t)((wm * 32 + (lane & 15)) * RB + (lane >> 4) * 16);
    const uint32_t boff = (uint32_t)((wn * 64 + ((lane >> 4) & 1) * 8 + (lane & 7)) * RB
                                     + ((lane >> 3) & 1) * 16);
    const uint32_t uBH = smem_u32(sBH), uBL = smem_u32(sBL);
    const uint32_t uA[2][2] = {{smem_u32(sA0H), smem_u32(sA0L)},
                               {smem_u32(sA1H), smem_u32(sA1L)}};
    char* pA[2][2] = {{sA0H, sA0L}, {sA1H, sA1L}};

    int buf = 0;
    for (int ti = x; ti < RTILES; ti += TPB) {
        int tn = ti + TPB;
        if (tn < RTILES) {
            tile_async(pA[buf ^ 1][0], pA[buf ^ 1][1],
                       g_hh + (size_t)tn * 128 * DD, g_hl + (size_t)tn * 128 * DD, tid);
            CP_COMMIT();
            CP_WAIT(1);
        } else {
            CP_WAIT(0);
        }
        __syncthreads();

        float acc[2][8][4];
        zero_acc(acc);
        mma_accum_3term(acc, uA[buf][0], uA[buf][1], uBH, uBL, aoff, boff);

        int row0 = ti * 128;
#pragma unroll
        for (int mi = 0; mi < 2; mi++) {
            int r0 = row0 + wm * 32 + mi * 16 + (lane >> 2);
#pragma unroll
            for (int n8 = 0; n8 < 8; n8++) {
                int col = wn * 64 + n8 * 8 + (lane & 3) * 2;
                float b0 = bias[tt * 128 + col], b1 = bias[tt * 128 + col + 1];
                if (r0 < NN)
                    *(float2*)(g_t + (size_t)r0 * 512 + tt * 128 + col) =
                        make_float2(acc[mi][n8][0] + b0, acc[mi][n8][1] + b1);
                if (r0 + 8 < NN)
                    *(float2*)(g_t + (size_t)(r0 + 8) * 512 + tt * 128 + col) =
                        make_float2(acc[mi][n8][2] + b0, acc[mi][n8][3] + b1);
            }
        }
        __syncthreads();       // buffer `buf` free for reuse next-next iteration
        buf ^= 1;
    }
}

// ---------------- gates: grid (391, 4), all-async fills -----------------
// y=0: rs = a@ih_r + h@hh_r ; y=1: zs ; y=2: in = a@ih_n ; y=3: hn = h@hh_n
__global__ __launch_bounds__(256, 1) void gates_tc() {
    extern __shared__ char smem[];
    char* sAaH = smem;
    char* sAaL = smem + AT128;
    char* sAhH = smem + 2 * AT128;
    char* sAhL = smem + 3 * AT128;
    char* sBH  = smem + 4 * AT128;
    char* sBL  = smem + 5 * AT128;
    const int tid = threadIdx.x, wid = tid >> 5, lane = tid & 31;
    const int wm = wid & 3, wn = wid >> 2;
    const int row0 = blockIdx.x * 128;
    const int y = blockIdx.y;
    const int ck = (y < 2) ? y : 2;

    if (y != 3) tile_async(sAaH, sAaL, g_ah + (size_t)row0 * DD, g_al + (size_t)row0 * DD, tid);
    if (y != 2) tile_async(sAhH, sAhL, g_hh + (size_t)row0 * DD, g_hl + (size_t)row0 * DD, tid);
    if (y == 3) tile_async(sBH, sBL, g_Bhh_hi + 2 * 16384, g_Bhh_lo + 2 * 16384, tid);
    else        tile_async(sBH, sBL, g_Bih_hi + ck * 16384, g_Bih_lo + ck * 16384, tid);
    CP_COMMIT();
    CP_WAIT(0);
    __syncthreads();

    const uint32_t aoff = (uint32_t)((wm * 32 + (lane & 15)) * RB + (lane >> 4) * 16);
    const uint32_t boff = (uint32_t)((wn * 64 + ((lane >> 4) & 1) * 8 + (lane & 7)) * RB
                                     + ((lane >> 3) & 1) * 16);
    float acc[2][8][4];
    zero_acc(acc);

    {   // pass 1: A = a (y=0,1,2) or h (y=3)
        uint32_t uH = (y == 3) ? smem_u32(sAhH) : smem_u32(sAaH);
        uint32_t uL = (y == 3) ? smem_u32(sAhL) : smem_u32(sAaL);
        mma_accum_3term(acc, uH, uL, smem_u32(sBH), smem_u32(sBL), aoff, boff);
    }
    if (y < 2) {  // pass 2: + h @ hh_ck
        __syncthreads();
        tile_async(sBH, sBL, g_Bhh_hi + ck * 16384, g_Bhh_lo + ck * 16384, tid);
        CP_COMMIT();
        CP_WAIT(0);
        __syncthreads();
        mma_accum_3term(acc, smem_u32(sAhH), smem_u32(sAhL),
                        smem_u32(sBH), smem_u32(sBL), aoff, boff);
    }

    float* C = (y == 0) ? g_rs : (y == 1) ? g_zs : (y == 2) ? g_in : g_hn;
#pragma unroll
    for (int mi = 0; mi < 2; mi++) {
        int r0 = row0 + wm * 32 + mi * 16 + (lane >> 2);
#pragma unroll
        for (int n8 = 0; n8 < 8; n8++) {
            int col = wn * 64 + n8 * 8 + (lane & 3) * 2;
            if (r0 < NN)
                *(float2*)(C + (size_t)r0 * DD + col) =
                    make_float2(acc[mi][n8][0], acc[mi][n8][1]);
            if (r0 + 8 < NN)
                *(float2*)(C + (size_t)(r0 + 8) * DD + col) =
                    make_float2(acc[mi][n8][2], acc[mi][n8][3]);
        }
    }
}

// ---------------- weight prep ----------------
__global__ void prep_wmsg(const float* __restrict__ Wmsg) {
    int idx = blockIdx.x * blockDim.x + threadIdx.x;
    if (idx >= TT * DD * DD) return;
    int t = idx >> 14, rem = idx & 16383, e = rem >> 7, d = rem & 127;
    float w = Wmsg[t * 16384 + d * 128 + e];
    __nv_bfloat16 hi, lo;
    split2(w, hi, lo);
    g_Wt_hi[idx] = hi;
    g_Wt_lo[idx] = lo;
}
__global__ void prep_gates(const float* __restrict__ wih, const float* __restrict__ whh) {
    int idx = blockIdx.x * blockDim.x + threadIdx.x;
    if (idx >= 3 * DD * DD) return;
    int c = idx >> 7, k = idx & 127;
    __nv_bfloat16 hi, lo;
    split2(wih[k * 384 + c], hi, lo);
    g_Bih_hi[idx] = hi; g_Bih_lo[idx] = lo;
    split2(whh[k * 384 + c], hi, lo);
    g_Bhh_hi[idx] = hi; g_Bhh_lo[idx] = lo;
}

// ---------------- init: h1 fp32; h split bf16 ----------------
__global__ void init_kernel(const float* __restrict__ features) {
    int idx = blockIdx.x * blockDim.x + threadIdx.x;
    if (idx >= NN * DD) return;
    int n = idx >> 7, j = idx & 127;
    float v = (j < DIN) ? features[n * DIN + j] : 0.f;
    g_h1[idx] = v;
    __nv_bfloat16 hi, lo;
    split2(v, hi, lo);
    g_hh[idx] = hi;
    g_hl[idx] = lo;
}

// ---------------- CSR build (by dst) ----------------
__global__ void zero_cnt_kernel() {
    int i = blockIdx.x * blockDim.x + threadIdx.x;
    if (i < NN) g_cnt[i] = 0;
}
__global__ void count_kernel(const int* __restrict__ dst) {
    int e = blockIdx.x * blockDim.x + threadIdx.x;
    if (e >= EE) return;
    g_eoff[e] = atomicAdd(&g_cnt[dst[e]], 1);
}
__global__ void scan_a_kernel() {
    __shared__ int s[256];
    int b = blockIdx.x, t = threadIdx.x;
    int n = b * 256 + t;
    int v = (n < NN) ? g_cnt[n] : 0;
    s[t] = v;
    __syncthreads();
    for (int d = 1; d < 256; d <<= 1) {
        int x = (t >= d) ? s[t - d] : 0;
        __syncthreads();
        s[t] += x;
        __syncthreads();
    }
    if (n < NN) g_scan[n] = s[t] - v;
    if (t == 255) g_part[b] = s[255];
}
__global__ void scan_b_kernel() {
    __shared__ int s[256];
    int t = threadIdx.x;
    int v = (t < NB1) ? g_part[t] : 0;
    s[t] = v;
    __syncthreads();
    for (int d = 1; d < 256; d <<= 1) {
        int x = (t >= d) ? s[t - d] : 0;
        __syncthreads();
        s[t] += x;
        __syncthreads();
    }
    g_part2[t] = s[t] - v;
}
__global__ void scan_c_kernel() {
    int n = blockIdx.x * blockDim.x + threadIdx.x;
    if (n < NN) g_off[n] = g_scan[n] + g_part2[n >> 8];
    if (n == 0) g_off[NN] = EE;
}
__global__ void fill_kernel(const int* __restrict__ src, const int* __restrict__ dst,
                            const int* __restrict__ et) {
    int e = blockIdx.x * blockDim.x + threadIdx.x;
    if (e >= EE) return;
    int pos = g_off[dst[e]] + g_eoff[e];
    g_gsrc[pos] = src[e] * 512 + et[e] * 128;
}

// ---------------- gather: a[d] = sum msgs; writes split bf16 ------------
__global__ __launch_bounds__(256) void gather_kernel() {
    int w = blockIdx.x * 8 + (threadIdx.x >> 5);
    if (w >= NN) return;
    int lane = threadIdx.x & 31;
    int b0 = g_off[w], b1 = g_off[w + 1];
    float4 a0 = make_float4(0.f, 0.f, 0.f, 0.f);
    float4 a1 = make_float4(0.f, 0.f, 0.f, 0.f);
    int i = b0;
    for (; i + 1 < b1; i += 2) {
        int s0 = g_gsrc[i], s1 = g_gsrc[i + 1];
        float4 v0 = *(const float4*)&g_t[s0 + lane * 4];
        float4 v1 = *(const float4*)&g_t[s1 + lane * 4];
        a0.x += v0.x; a0.y += v0.y; a0.z += v0.z; a0.w += v0.w;
        a1.x += v1.x; a1.y += v1.y; a1.z += v1.z; a1.w += v1.w;
    }
    if (i < b1) {
        int s0 = g_gsrc[i];
        float4 v0 = *(const float4*)&g_t[s0 + lane * 4];
        a0.x += v0.x; a0.y += v0.y; a0.z += v0.z; a0.w += v0.w;
    }
    a0.x += a1.x; a0.y += a1.y; a0.z += a1.z; a0.w += a1.w;

    __nv_bfloat16 h0, l0, h1, l1, h2, l2, h3, l3;
    split2(a0.x, h0, l0); split2(a0.y, h1, l1);
    split2(a0.z, h2, l2); split2(a0.w, h3, l3);
    __nv_bfloat162 hp0 = {h0, h1}, hp1 = {h2, h3};
    __nv_bfloat162 lp0 = {l0, l1}, lp1 = {l2, l3};
    size_t o = (size_t)w * DD + lane * 4;
    *(uint2*)(g_ah + o) = make_uint2(*(uint32_t*)&hp0, *(uint32_t*)&hp1);
    *(uint2*)(g_al + o) = make_uint2(*(uint32_t*)&lp0, *(uint32_t*)&lp1);
}

// ---------------- GRU pointwise: writes split h ----------------
__global__ void gru_kernel(const float* __restrict__ bih, const float* __restrict__ bhh) {
    int idx = blockIdx.x * blockDim.x + threadIdx.x;
    if (idx >= NN * 32) return;
    int n = idx >> 5, q = idx & 31;
    int col = q * 4;
    size_t o = (size_t)n * DD + col;
    float4 rs = *(const float4*)&g_rs[o];
    float4 zs = *(const float4*)&g_zs[o];
    float4 iv = *(const float4*)&g_in[o];
    float4 hv = *(const float4*)&g_hn[o];
    // reconstruct h from split
    uint2 hhp = *(const uint2*)(g_hh + o);
    uint2 hlp = *(const uint2*)(g_hl + o);
    __nv_bfloat162 hh0 = *(__nv_bfloat162*)&hhp.x, hh1 = *(__nv_bfloat162*)&hhp.y;
    __nv_bfloat162 hl0 = *(__nv_bfloat162*)&hlp.x, hl1 = *(__nv_bfloat162*)&hlp.y;
    float hx = __bfloat162float(hh0.x) + __bfloat162float(hl0.x);
    float hy = __bfloat162float(hh0.y) + __bfloat162float(hl0.y);
    float hz = __bfloat162float(hh1.x) + __bfloat162float(hl1.x);
    float hw = __bfloat162float(hh1.y) + __bfloat162float(hl1.y);

    float4 br  = *(const float4*)&bih[col];
    float4 br2 = *(const float4*)&bhh[col];
    float4 bz  = *(const float4*)&bih[128 + col];
    float4 bz2 = *(const float4*)&bhh[128 + col];
    float4 bn  = *(const float4*)&bih[256 + col];
    float4 bn2 = *(const float4*)&bhh[256 + col];
    float out[4];
    float hin[4] = {hx, hy, hz, hw};
    float rsv[4] = {rs.x, rs.y, rs.z, rs.w};
    float zsv[4] = {zs.x, zs.y, zs.z, zs.w};
    float ivv[4] = {iv.x, iv.y, iv.z, iv.w};
    float hvv[4] = {hv.x, hv.y, hv.z, hv.w};
    float brv[4] = {br.x + br2.x, br.y + br2.y, br.z + br2.z, br.w + br2.w};
    float bzv[4] = {bz.x + bz2.x, bz.y + bz2.y, bz.z + bz2.z, bz.w + bz2.w};
    float bnv[4] = {bn.x, bn.y, bn.z, bn.w};
    float bn2v[4] = {bn2.x, bn2.y, bn2.z, bn2.w};
#pragma unroll
    for (int j = 0; j < 4; j++) {
        float r = 1.f / (1.f + expf(-(rsv[j] + brv[j])));
        float z = 1.f / (1.f + expf(-(zsv[j] + bzv[j])));
        float ng = tanhf(ivv[j] + bnv[j] + r * (hvv[j] + bn2v[j]));
        out[j] = (1.f - z) * ng + z * hin[j];
    }
    __nv_bfloat16 oh[4], ol[4];
#pragma unroll
    for (int j = 0; j < 4; j++) split2(out[j], oh[j], ol[j]);
    __nv_bfloat162 ohp0 = {oh[0], oh[1]}, ohp1 = {oh[2], oh[3]};
    __nv_bfloat162 olp0 = {ol[0], ol[1]}, olp1 = {ol[2], ol[3]};
    *(uint2*)(g_hh + o) = make_uint2(*(uint32_t*)&ohp0, *(uint32_t*)&ohp1);
    *(uint2*)(g_hl + o) = make_uint2(*(uint32_t*)&olp0, *(uint32_t*)&olp1);
}

// ---------------- pooling + classifier ----------------
__global__ void zero_feats_kernel() {
    int i = blockIdx.x * blockDim.x + threadIdx.x;
    if (i < BG * DD) g_feats[i] = 0.f;
}
__global__ void pool_kernel(const int* __restrict__ n2g) {
    int n0 = blockIdx.x * 64;
    int j  = threadIdx.x;
    if (n0 >= NN) return;
    float acc = 0.f;
    int cur = n2g[n0];
    for (int i = 0; i < 64; i++) {
        int n = n0 + i;
        if (n >= NN) break;
        int g = n2g[n];
        if (g != cur) {
            atomicAdd(&g_feats[cur * DD + j], acc);
            acc = 0.f; cur = g;
        }
        size_t o = (size_t)n * DD + j;
        float h = __bfloat162float(g_hh[o]) + __bfloat162float(g_hl[o]);
        acc += h + g_h1[o];
    }
    atomicAdd(&g_feats[cur * DD + j], acc);
}
__global__ void cls_kernel(const float* __restrict__ Wc,
                           const float* __restrict__ bc,
                           float* __restrict__ out) {
    int tid = threadIdx.x;
    if (tid >= BG * 2) return;
    int g = tid >> 1, c = tid & 1;
    float s = bc[c];
#pragma unroll 8
    for (int k = 0; k < DD; k++) s += g_feats[g * DD + k] * Wc[k * 2 + c];
    out[g * 2 + c] = s;
}

// ---------------- launch ----------------
extern "C" void kernel_launch(void* const* d_in, const int* in_sizes, int n_in,
                              void* d_out, int out_size) {
    const float* features = (const float*)d_in[0];
    const int*   src      = (const int*)  d_in[1];
    const int*   dst      = (const int*)  d_in[2];
    const int*   etype    = (const int*)  d_in[3];
    const int*   n2g      = (const int*)  d_in[4];
    const float* W_msg    = (const float*)d_in[5];
    const float* b_msg    = (const float*)d_in[6];
    const float* w_ih     = (const float*)d_in[7];
    const float* b_ih     = (const float*)d_in[8];
    const float* w_hh     = (const float*)d_in[9];
    const float* b_hh     = (const float*)d_in[10];
    const float* W_cls    = (const float*)d_in[11];
    const float* b_cls    = (const float*)d_in[12];
    float* out = (float*)d_out;

    static int inited = 0;
    if (!inited) {
        cudaFuncSetAttribute(transform_tc,
                             cudaFuncAttributeMaxDynamicSharedMemorySize, SM6);
        cudaFuncSetAttribute(gates_tc,
                             cudaFuncAttributeMaxDynamicSharedMemorySize, SM6);
        inited = 1;
    }

    // prologue
    prep_wmsg<<<(TT * DD * DD + 255) / 256, 256>>>(W_msg);
    prep_gates<<<(3 * DD * DD + 255) / 256, 256>>>(w_ih, w_hh);
    init_kernel<<<(NN * DD + 255) / 256, 256>>>(features);
    zero_cnt_kernel<<<(NN + 255) / 256, 256>>>();
    count_kernel<<<(EE + 255) / 256, 256>>>(dst);
    scan_a_kernel<<<NB1, 256>>>();
    scan_b_kernel<<<1, 256>>>();
    scan_c_kernel<<<(NN + 255) / 256, 256>>>();
    fill_kernel<<<(EE + 255) / 256, 256>>>(src, dst, etype);

    for (int s = 0; s < NSTEPS; s++) {
        transform_tc<<<dim3(TPB, TT), 256, SM6>>>(b_msg);
        gather_kernel<<<(NN + 7) / 8, 256>>>();
        gates_tc<<<dim3(RTILES, 4), 256, SM6>>>();
        gru_kernel<<<(NN * 32 + 255) / 256, 256>>>(b_ih, b_hh);
    }

    zero_feats_kernel<<<(BG * DD + 255) / 256, 256>>>();
    pool_kernel<<<(NN + 63) / 64, 128>>>(n2g);
    cls_kernel<<<1, 128>>>(W_cls, b_cls, out);
}